// round 5
// baseline (speedup 1.0000x reference)
#include <cuda_runtime.h>
#include <cuda_fp16.h>

// ---------------------------------------------------------------------------
// HMPNN layer, R5: U-table factorization + src-sorted edge processing.
//   U[n,f,o] = sum_i x_src[n,i] * w_msg[f,i,o]   (f=16 block = xj@b_msg)
//   msg[e,o] = U[src,16,o] + sum_f ea[e,f] * U[src,f,o]
//   Edges counting-sorted by src each call -> U gather is L1-hot.
// ---------------------------------------------------------------------------

#define NMAX 50000
#define EMAX 1000000
#define UROW 272              // 17 f-blocks * 16 outputs

typedef unsigned long long ull;

__device__ float  g_agg[2][NMAX * 16];
__device__ __half g_U[2][NMAX * UROW];
__device__ int    g_cnt[2][NMAX];
__device__ int    g_offs[2][NMAX];
__device__ int    g_cur[2][NMAX];
__device__ int2   g_sd[2][EMAX];     // (src,dst) sorted by src
__device__ int    g_ord[2][EMAX];    // original edge id, sorted by src

__device__ __forceinline__ ull pk2(float x, float y) {
    ull r;
    asm("mov.b64 %0, {%1,%2};" : "=l"(r)
        : "r"(__float_as_uint(x)), "r"(__float_as_uint(y)));
    return r;
}
__device__ __forceinline__ void unpk2(ull a, float& x, float& y) {
    unsigned lo, hi;
    asm("mov.b64 {%0,%1}, %2;" : "=r"(lo), "=r"(hi) : "l"(a));
    x = __uint_as_float(lo);
    y = __uint_as_float(hi);
}
__device__ __forceinline__ ull fma2(ull a, ull b, ull c) {
    ull r;
    asm("fma.rn.f32x2 %0, %1, %2, %3;" : "=l"(r) : "l"(a), "l"(b), "l"(c));
    return r;
}
__device__ __forceinline__ void red4(float* p, float a, float b, float c, float d) {
    asm volatile("red.global.add.v4.f32 [%0], {%1,%2,%3,%4};"
                 :: "l"(p), "f"(a), "f"(b), "f"(c), "f"(d) : "memory");
}
__device__ __forceinline__ float sigmoidf(float x) {
    return 1.0f / (1.0f + __expf(-x));
}

// ---------------------------------------------------------------------------
// init: agg = bias + x_indivi@root; also zero the CSR counters
// ---------------------------------------------------------------------------
__global__ __launch_bounds__(128) void init_kernel(
    const float* __restrict__ x_indivi,
    const float* __restrict__ root_a, const float* __restrict__ bias_a,
    const float* __restrict__ root_b, const float* __restrict__ bias_b,
    int N) {
    int n = blockIdx.x * 128 + threadIdx.x;
    if (n >= N) return;
    g_cnt[0][n] = 0;
    g_cnt[1][n] = 0;

    float x[16];
    const float4* xr = (const float4*)(x_indivi + n * 16);
#pragma unroll
    for (int j = 0; j < 4; ++j) {
        float4 v = xr[j];
        x[4 * j + 0] = v.x; x[4 * j + 1] = v.y;
        x[4 * j + 2] = v.z; x[4 * j + 3] = v.w;
    }
    float sa[16], sb[16];
#pragma unroll
    for (int o = 0; o < 16; ++o) { sa[o] = bias_a[o]; sb[o] = bias_b[o]; }
#pragma unroll
    for (int i = 0; i < 16; ++i) {
#pragma unroll
        for (int o = 0; o < 16; ++o) {
            sa[o] += x[i] * root_a[i * 16 + o];
            sb[o] += x[i] * root_b[i * 16 + o];
        }
    }
#pragma unroll
    for (int o = 0; o < 16; ++o) {
        g_agg[0][n * 16 + o] = sa[o];
        g_agg[1][n * 16 + o] = sb[o];
    }
}

// ---------------------------------------------------------------------------
// hist: per-src degree count (blockIdx.y = step)
// ---------------------------------------------------------------------------
__global__ __launch_bounds__(256) void hist_kernel(
    const int* __restrict__ ei_a, const int* __restrict__ ei_b, int E) {
    int e = blockIdx.x * 256 + threadIdx.x;
    if (e >= E) return;
    int step = blockIdx.y;
    const int* ei = step ? ei_b : ei_a;
    atomicAdd(&g_cnt[step][ei[e]], 1);
}

// ---------------------------------------------------------------------------
// scan: exclusive prefix over 50k counters (1 block per step)
// ---------------------------------------------------------------------------
__global__ __launch_bounds__(1024) void scan_kernel(int N) {
    const int step = blockIdx.x;
    const int t = threadIdx.x;
    const int chunk = (N + 1023) / 1024;
    const int lo = t * chunk;
    const int hi = min(lo + chunk, N);

    int mysum = 0;
    for (int j = lo; j < hi; ++j) mysum += g_cnt[step][j];

    __shared__ int sh[1024];
    sh[t] = mysum;
    __syncthreads();
    for (int off = 1; off < 1024; off <<= 1) {
        int v = (t >= off) ? sh[t - off] : 0;
        __syncthreads();
        sh[t] += v;
        __syncthreads();
    }
    int run = sh[t] - mysum;   // exclusive base for this thread's chunk

    for (int j = lo; j < hi; ++j) {
        int c = g_cnt[step][j];
        g_offs[step][j] = run;
        g_cur[step][j] = run;
        run += c;
    }
}

// ---------------------------------------------------------------------------
// scatter: place each edge into its src bucket (blockIdx.y = step)
// ---------------------------------------------------------------------------
__global__ __launch_bounds__(256) void scatter_kernel(
    const int* __restrict__ ei_a, const int* __restrict__ ei_b, int E) {
    int e = blockIdx.x * 256 + threadIdx.x;
    if (e >= E) return;
    int step = blockIdx.y;
    const int* ei = step ? ei_b : ei_a;
    int s = ei[e];
    int d = ei[E + e];
    int p = atomicAdd(&g_cur[step][s], 1);
    g_ord[step][p] = e;
    g_sd[step][p] = make_int2(s, d);
}

// ---------------------------------------------------------------------------
// u_kernel: build fp16 U table, 2 nodes per thread via f32x2
// ---------------------------------------------------------------------------
__global__ __launch_bounds__(128) void u_kernel(
    const float* __restrict__ xs,
    const float* __restrict__ wm,
    const float* __restrict__ bm,
    __half* __restrict__ U,
    int N) {
    __shared__ __align__(16) ull w2[17 * 256];  // [f][i][o], dup lanes; f=16 = b_msg
    for (int k = threadIdx.x; k < 4096; k += 128) {
        float v = wm[k];
        w2[k] = pk2(v, v);
    }
    for (int k = threadIdx.x; k < 256; k += 128) {
        float v = bm[k];
        w2[4096 + k] = pk2(v, v);
    }
    __syncthreads();

    int t = blockIdx.x * 128 + threadIdx.x;
    int n0 = 2 * t;
    if (n0 >= N) return;
    int n1 = min(n0 + 1, N - 1);

    ull xj[16];
    {
        const float4* x0 = (const float4*)(xs + n0 * 16);
        const float4* x1 = (const float4*)(xs + n1 * 16);
#pragma unroll
        for (int j = 0; j < 4; ++j) {
            float4 a = x0[j], b = x1[j];
            xj[4 * j + 0] = pk2(a.x, b.x);
            xj[4 * j + 1] = pk2(a.y, b.y);
            xj[4 * j + 2] = pk2(a.z, b.z);
            xj[4 * j + 3] = pk2(a.w, b.w);
        }
    }

    __half* U0 = U + n0 * UROW;
    __half* U1 = U + n1 * UROW;
    bool two = (n1 != n0);

#pragma unroll 1
    for (int f = 0; f < 17; ++f) {
        const ull* Wf = w2 + f * 256;
        ull acc[16];
#pragma unroll
        for (int o = 0; o < 16; ++o) acc[o] = 0;
#pragma unroll
        for (int i = 0; i < 16; ++i) {
            ull xi = xj[i];
            const ull* wr = Wf + i * 16;
#pragma unroll
            for (int o = 0; o < 16; ++o)
                acc[o] = fma2(xi, wr[o], acc[o]);
        }
        __half2 h0[8], h1[8];
#pragma unroll
        for (int j = 0; j < 8; ++j) {
            float a0, b0, a1, b1;
            unpk2(acc[2 * j], a0, b0);
            unpk2(acc[2 * j + 1], a1, b1);
            h0[j] = __floats2half2_rn(a0, a1);
            h1[j] = __floats2half2_rn(b0, b1);
        }
        uint4* d0 = (uint4*)(U0 + f * 16);
        d0[0] = *(const uint4*)&h0[0];
        d0[1] = *(const uint4*)&h0[4];
        if (two) {
            uint4* d1 = (uint4*)(U1 + f * 16);
            d1[0] = *(const uint4*)&h1[0];
            d1[1] = *(const uint4*)&h1[4];
        }
    }
}

// ---------------------------------------------------------------------------
// edge: src-sorted order; 2 lanes per edge, lane l owns outputs 8l..8l+7
// ---------------------------------------------------------------------------
__global__ __launch_bounds__(256) void edge_kernel(
    const float* __restrict__ eat,
    const __half* __restrict__ U,
    const int* __restrict__ ord,
    const int2* __restrict__ sd,
    float* __restrict__ agg,
    int E) {
    int t = blockIdx.x * 256 + threadIdx.x;
    int idx = t >> 1;
    int l = t & 1;
    if (idx >= E) return;

    int e = __ldg(ord + idx);
    int2 p = __ldg(sd + idx);
    int s = p.x, d = p.y;

    const uint4* __restrict__ Ur = (const uint4*)(U + s * UROW) + l;
    const float4* __restrict__ ear = (const float4*)(eat + e * 16);

    float4 ea0 = __ldg(ear + 0);
    float4 ea1 = __ldg(ear + 1);
    float4 ea2 = __ldg(ear + 2);
    float4 ea3 = __ldg(ear + 3);
    float ea[16] = {ea0.x, ea0.y, ea0.z, ea0.w,
                    ea1.x, ea1.y, ea1.z, ea1.w,
                    ea2.x, ea2.y, ea2.z, ea2.w,
                    ea3.x, ea3.y, ea3.z, ea3.w};

    float4 accL, accH;
    {
        uint4 u = __ldg(Ur + 32);   // bias block f=16
        const __half2* h = (const __half2*)&u;
        float2 f0 = __half22float2(h[0]);
        float2 f1 = __half22float2(h[1]);
        float2 f2 = __half22float2(h[2]);
        float2 f3 = __half22float2(h[3]);
        accL = make_float4(f0.x, f0.y, f1.x, f1.y);
        accH = make_float4(f2.x, f2.y, f3.x, f3.y);
    }

#pragma unroll
    for (int r = 0; r < 16; ++r) {
        uint4 u = __ldg(Ur + r * 2);
        float er = ea[r];
        const __half2* h = (const __half2*)&u;
        float2 f0 = __half22float2(h[0]);
        float2 f1 = __half22float2(h[1]);
        float2 f2 = __half22float2(h[2]);
        float2 f3 = __half22float2(h[3]);
        accL.x += er * f0.x; accL.y += er * f0.y;
        accL.z += er * f1.x; accL.w += er * f1.y;
        accH.x += er * f2.x; accH.y += er * f2.y;
        accH.z += er * f3.x; accH.w += er * f3.y;
    }

    float* base = &agg[d * 16 + 8 * l];
    red4(base,     accL.x, accL.y, accL.z, accL.w);
    red4(base + 4, accH.x, accH.y, accH.z, accH.w);
}

// ---------------------------------------------------------------------------
// final: 2 lanes per node; lane l computes outputs 16l..16l+15
// ---------------------------------------------------------------------------
__global__ __launch_bounds__(256) void final_kernel(
    const float* __restrict__ w_lin,
    const float* __restrict__ b_lin,
    float* __restrict__ out, int N) {
    __shared__ __align__(16) float wl[32 * 32];
    __shared__ float bl[32];
    for (int k = threadIdx.x; k < 1024; k += 256) wl[k] = w_lin[k];
    if (threadIdx.x < 32) bl[threadIdx.x] = b_lin[threadIdx.x];
    __syncthreads();

    int t = blockIdx.x * 256 + threadIdx.x;
    int n = t >> 1;
    int l = t & 1;
    if (n >= N) return;

    float s[32];
    {
        const float4* ga = (const float4*)(&g_agg[0][n * 16]);
        const float4* gb = (const float4*)(&g_agg[1][n * 16]);
#pragma unroll
        for (int j = 0; j < 4; ++j) {
            float4 va = ga[j];
            s[4 * j + 0] = sigmoidf(va.x); s[4 * j + 1] = sigmoidf(va.y);
            s[4 * j + 2] = sigmoidf(va.z); s[4 * j + 3] = sigmoidf(va.w);
        }
#pragma unroll
        for (int j = 0; j < 4; ++j) {
            float4 vb = gb[j];
            s[16 + 4 * j + 0] = sigmoidf(vb.x); s[16 + 4 * j + 1] = sigmoidf(vb.y);
            s[16 + 4 * j + 2] = sigmoidf(vb.z); s[16 + 4 * j + 3] = sigmoidf(vb.w);
        }
    }

    float4 acc[4];
#pragma unroll
    for (int j = 0; j < 4; ++j) {
        int o = 16 * l + 4 * j;
        acc[j] = make_float4(bl[o], bl[o + 1], bl[o + 2], bl[o + 3]);
    }
#pragma unroll
    for (int k = 0; k < 32; ++k) {
        float sk = s[k];
        const float4* w4 = (const float4*)(wl + k * 32 + 16 * l);
#pragma unroll
        for (int j = 0; j < 4; ++j) {
            float4 w = w4[j];
            acc[j].x += sk * w.x;
            acc[j].y += sk * w.y;
            acc[j].z += sk * w.z;
            acc[j].w += sk * w.w;
        }
    }

    float4* o4 = (float4*)(out + n * 32 + 16 * l);
#pragma unroll
    for (int j = 0; j < 4; ++j)
        o4[j] = make_float4(sigmoidf(acc[j].x), sigmoidf(acc[j].y),
                            sigmoidf(acc[j].z), sigmoidf(acc[j].w));
}

// ---------------------------------------------------------------------------
extern "C" void kernel_launch(void* const* d_in, const int* in_sizes, int n_in,
                              void* d_out, int out_size) {
    const float* x_indivi = (const float*)d_in[0];
    const float* x_src_a  = (const float*)d_in[1];
    const float* x_src_b  = (const float*)d_in[2];
    const int*   ei_a     = (const int*)d_in[3];
    const int*   ei_b     = (const int*)d_in[4];
    const float* ea_a     = (const float*)d_in[5];
    const float* ea_b     = (const float*)d_in[6];
    const float* wm_a     = (const float*)d_in[7];
    const float* bm_a     = (const float*)d_in[8];
    const float* root_a   = (const float*)d_in[9];
    const float* bias_a   = (const float*)d_in[10];
    const float* wm_b     = (const float*)d_in[11];
    const float* bm_b     = (const float*)d_in[12];
    const float* root_b   = (const float*)d_in[13];
    const float* bias_b   = (const float*)d_in[14];
    const float* w_lin    = (const float*)d_in[15];
    const float* b_lin    = (const float*)d_in[16];
    float* out = (float*)d_out;

    int N = in_sizes[0] / 16;
    int E = in_sizes[3] / 2;   // edge_index is [2, E]

    float* agg_base;  __half* U_base;
    int* ord_base;    int2* sd_base;
    cudaGetSymbolAddress((void**)&agg_base, g_agg);
    cudaGetSymbolAddress((void**)&U_base, g_U);
    cudaGetSymbolAddress((void**)&ord_base, g_ord);
    cudaGetSymbolAddress((void**)&sd_base, g_sd);
    float*  agg_a = agg_base;
    float*  agg_b = agg_base + NMAX * 16;
    __half* U_a = U_base;
    __half* U_b = U_base + NMAX * UROW;
    int*  ord_a = ord_base;
    int*  ord_b = ord_base + EMAX;
    int2* sd_a = sd_base;
    int2* sd_b = sd_base + EMAX;

    int nb128 = (N + 127) / 128;
    int eb = (E + 255) / 256;
    int eb2 = (2 * E + 255) / 256;

    // 1: init (agg + zero counters)
    init_kernel<<<nb128, 128>>>(x_indivi, root_a, bias_a, root_b, bias_b, N);
    // 2: histogram both steps
    hist_kernel<<<dim3(eb, 2), 256>>>(ei_a, ei_b, E);
    // 3: scan both steps
    scan_kernel<<<2, 1024>>>(N);
    // 4: scatter both steps
    scatter_kernel<<<dim3(eb, 2), 256>>>(ei_a, ei_b, E);
    // 5: U table step a
    u_kernel<<<(N / 2 + 127) / 128, 128>>>(x_src_a, wm_a, bm_a, U_a, N);
    // 6: edge step a  (ncu -s 5 lands here)
    edge_kernel<<<eb2, 256>>>(ea_a, U_a, ord_a, sd_a, agg_a, E);
    // 7: U table step b
    u_kernel<<<(N / 2 + 127) / 128, 128>>>(x_src_b, wm_b, bm_b, U_b, N);
    // 8: edge step b
    edge_kernel<<<eb2, 256>>>(ea_b, U_b, ord_b, sd_b, agg_b, E);
    // 9: final
    final_kernel<<<(2 * N + 255) / 256, 256>>>(w_lin, b_lin, out, N);
}